// round 7
// baseline (speedup 1.0000x reference)
#include <cuda_runtime.h>

#define LSEQ    2048
#define BATCH   32
#define TPB     256
#define NCHUNK  16
#define CHQ     128           // queries per chunk
#define DT_C    0.01f
#define EPS_C   1e-5f
#define QS_C    (1.4426950408889634f * 0.57735026918962576f)  // log2e/sqrt(3)

typedef unsigned long long ull;

__device__ __forceinline__ ull fma2(ull a, ull b, ull c) {
    ull d; asm("fma.rn.f32x2 %0, %1, %2, %3;" : "=l"(d) : "l"(a), "l"(b), "l"(c)); return d;
}
__device__ __forceinline__ ull mul2(ull a, ull b) {
    ull d; asm("mul.rn.f32x2 %0, %1, %2;" : "=l"(d) : "l"(a), "l"(b)); return d;
}
__device__ __forceinline__ ull add2(ull a, ull b) {
    ull d; asm("add.rn.f32x2 %0, %1, %2;" : "=l"(d) : "l"(a), "l"(b)); return d;
}
__device__ __forceinline__ ull pk2(float lo, float hi) {
    ull r; asm("mov.b64 %0, {%1, %2};" : "=l"(r) : "f"(lo), "f"(hi)); return r;
}
__device__ __forceinline__ void up2(ull v, float& lo, float& hi) {
    asm("mov.b64 {%0, %1}, %2;" : "=f"(lo), "=f"(hi) : "l"(v));
}
__device__ __forceinline__ float ex2f(float x) {
    float y; asm("ex2.approx.ftz.f32 %0, %1;" : "=f"(y) : "f"(x)); return y;
}

// ================= single fused kernel =================
// block = (batch, chunk); 256 threads = 2 warpgroups, one K-segment each.
__global__ void __launch_bounds__(TPB, 4)
fused_kernel(const float* __restrict__ inp,
             const float* __restrict__ ipw, const float* __restrict__ ipb,
             const float* __restrict__ opw, const float* __restrict__ opb,
             const float* __restrict__ f1w, const float* __restrict__ f1b,
             const float* __restrict__ f2w, const float* __restrict__ f2b,
             const float* __restrict__ g1w, const float* __restrict__ g1b,
             const float* __restrict__ g2w, const float* __restrict__ g2b,
             const float* __restrict__ m1p, const float* __restrict__ m2p,
             const float* __restrict__ sig,
             float* __restrict__ out)
{
    extern __shared__ float4 sm[];
    float4* sP  = sm;              // [1024] (k0e,k0o,k1e,k1o)
    float4* sQ  = sm + 1024;       // [1024] (k2e,k2o,v0e,v0o)
    float4* sR  = sm + 2048;       // [1024] (v1e,v1o,v2e,v2o)
    float4* red = sm + 3072;       // [256]  per-(q,seg) partials

    const int b  = blockIdx.x;
    const int c  = (NCHUNK - 1) - blockIdx.y;     // long chunks first (LPT)
    const int t  = threadIdx.x;
    const int wg = t >> 7;                        // segment 0 / 1
    const int wt = t & (CHQ - 1);
    const int q  = c * CHQ + wt;

    const int npref = 64 * (c + 1);               // staged causal pairs
    const int segl  = 32 * (c + 1);
    const int s0 = wg * segl, s1 = s0 + segl;

    const float inv0 = 1.0f / (__ldg(&sig[0]) + EPS_C);
    const float inv1 = 1.0f / (__ldg(&sig[1]) + EPS_C);
    const float* xb = inp + ((size_t)b * LSEQ) * 3;

    // ---- stage: project causal-prefix K/V pairs into smem (all 256 threads) ----
    {
        float WK[9], WV[9], BK[3], BV[3];
        #pragma unroll
        for (int k = 0; k < 9; k++) { WK[k] = __ldg(&ipw[9 + k]); WV[k] = __ldg(&ipw[18 + k]); }
        #pragma unroll
        for (int k = 0; k < 3; k++) { BK[k] = __ldg(&ipb[3 + k]); BV[k] = __ldg(&ipb[6 + k]); }

        for (int i = t; i < npref; i += TPB) {
            const float2* xp = (const float2*)(xb + 6 * i);
            float2 u0 = __ldg(&xp[0]);
            float2 u1 = __ldg(&xp[1]);
            float2 u2 = __ldg(&xp[2]);
            float xe0 = u0.x, xe1 = u0.y * inv0, xe2 = u1.x * inv1;
            float xo0 = u1.y, xo1 = u2.x * inv0, xo2 = u2.y * inv1;
            float ke[3], ko[3], ve[3], vo[3];
            #pragma unroll
            for (int r = 0; r < 3; r++) {
                ke[r] = fmaf(WK[3*r], xe0, fmaf(WK[3*r+1], xe1, fmaf(WK[3*r+2], xe2, BK[r])));
                ko[r] = fmaf(WK[3*r], xo0, fmaf(WK[3*r+1], xo1, fmaf(WK[3*r+2], xo2, BK[r])));
                ve[r] = fmaf(WV[3*r], xe0, fmaf(WV[3*r+1], xe1, fmaf(WV[3*r+2], xe2, BV[r])));
                vo[r] = fmaf(WV[3*r], xo0, fmaf(WV[3*r+1], xo1, fmaf(WV[3*r+2], xo2, BV[r])));
            }
            sP[i] = make_float4(ke[0], ko[0], ke[1], ko[1]);
            sQ[i] = make_float4(ke[2], ko[2], ve[0], vo[0]);
            sR[i] = make_float4(ve[1], vo[1], ve[2], vo[2]);
        }
    }

    // ---- own query (both warpgroups compute the same q's vector) ----
    ull qp0, qp1, qp2;
    {
        const float* xq = xb + q * 3;
        float x0 = __ldg(&xq[0]), x1 = __ldg(&xq[1]) * inv0, x2 = __ldg(&xq[2]) * inv1;
        float q0 = fmaf(__ldg(&ipw[0]), x0, fmaf(__ldg(&ipw[1]), x1, fmaf(__ldg(&ipw[2]), x2, __ldg(&ipb[0])))) * QS_C;
        float q1 = fmaf(__ldg(&ipw[3]), x0, fmaf(__ldg(&ipw[4]), x1, fmaf(__ldg(&ipw[5]), x2, __ldg(&ipb[1])))) * QS_C;
        float q2 = fmaf(__ldg(&ipw[6]), x0, fmaf(__ldg(&ipw[7]), x1, fmaf(__ldg(&ipw[8]), x2, __ldg(&ipb[2])))) * QS_C;
        qp0 = pk2(q0, q0); qp1 = pk2(q1, q1); qp2 = pk2(q2, q2);
    }

    __syncthreads();

    // ---- warp-uniform causal split within this segment ----
    const int qbase = c * CHQ + (wt & ~31);
    const int lbmin = (qbase - 1) >> 1;
    const int lamax = (qbase + 31) >> 1;
    const int B1 = min(s1, max(s0, lbmin + 1));   // [s0,B1): valid for all lanes
    const int B2 = min(s1, max(s0, lamax + 1));   // [B1,B2): diagonal band
    const int la = q >> 1;
    const int lb = (q - 1) >> 1;

    const ulonglong2* pP = (const ulonglong2*)sP;
    const ulonglong2* pQ = (const ulonglong2*)sQ;
    const ulonglong2* pR = (const ulonglong2*)sR;

    ull sum2 = 0ull, a02 = 0ull, a12 = 0ull, a22 = 0ull;

    #pragma unroll 4
    for (int i = s0; i < B1; i++) {               // unmasked bulk
        ulonglong2 Pv = pP[i];
        ulonglong2 Qv = pQ[i];
        ulonglong2 Rv = pR[i];
        ull sc = fma2(Pv.x, qp0, fma2(Pv.y, qp1, mul2(Qv.x, qp2)));
        float se, so; up2(sc, se, so);
        ull p = pk2(ex2f(se), ex2f(so));
        sum2 = add2(sum2, p);
        a02 = fma2(p, Qv.y, a02);
        a12 = fma2(p, Rv.x, a12);
        a22 = fma2(p, Rv.y, a22);
    }
    for (int i = B1; i < B2; i++) {               // diagonal band (<=17 iters)
        ulonglong2 Pv = pP[i];
        ulonglong2 Qv = pQ[i];
        ulonglong2 Rv = pR[i];
        ull sc = fma2(Pv.x, qp0, fma2(Pv.y, qp1, mul2(Qv.x, qp2)));
        float se, so; up2(sc, se, so);
        float plo = (i <= la) ? ex2f(se) : 0.0f;
        float phi = (i <= lb) ? ex2f(so) : 0.0f;
        ull p = pk2(plo, phi);
        sum2 = add2(sum2, p);
        a02 = fma2(p, Qv.y, a02);
        a12 = fma2(p, Rv.x, a12);
        a22 = fma2(p, Rv.y, a22);
    }

    float sl, sh, c0l, c0h, c1l, c1h, c2l, c2h;
    up2(sum2, sl, sh); up2(a02, c0l, c0h); up2(a12, c1l, c1h); up2(a22, c2l, c2h);
    red[wt * 2 + wg] = make_float4(sl + sh, c0l + c0h, c1l + c1h, c2l + c2h);

    __syncthreads();

    // ---- combine + out-proj + ODE epilogue (warpgroup 0 only) ----
    if (wg == 0) {
        float4 A = red[wt * 2];
        float4 Bp = red[wt * 2 + 1];
        float cs = A.x + Bp.x, c0 = A.y + Bp.y, c1 = A.z + Bp.z, c2 = A.w + Bp.w;

        const float sc0 = 1.0f / inv0;            // == sig0 + EPS (exact: recompute)
        const float sc1 = 1.0f / inv1;
        float wo[9];
        #pragma unroll
        for (int i = 0; i < 9; i++) wo[i] = __ldg(&opw[i]);
        const float bo1 = __ldg(&opb[1]), bo2 = __ldg(&opb[2]);
        const float m1 = __ldg(m1p), m2 = __ldg(m2p);
        float F1[3], F2[3], G1[3], G2[3];
        #pragma unroll
        for (int i = 0; i < 3; i++) {
            F1[i] = __ldg(&f1w[i]); F2[i] = __ldg(&f2w[i]);
            G1[i] = __ldg(&g1w[i]); G2[i] = __ldg(&g2w[i]);
        }
        const float F1b = __ldg(f1b), F2b = __ldg(f2b), G1b = __ldg(g1b), G2b = __ldg(g2b);

        float inv = 1.0f / cs;
        float x0 = c0 * inv, x1 = c1 * inv, x2 = c2 * inv;
        float s1v = fmaf(wo[3], x0, fmaf(wo[4], x1, fmaf(wo[5], x2, bo1)));
        float s2v = fmaf(wo[6], x0, fmaf(wo[7], x1, fmaf(wo[8], x2, bo2)));

        float S2_1, S2_2, S3_1, S3_2, S4_1, S4_2;
        {
            float g1v = (G1[0] + fmaf(G1[1], s1v, fmaf(G1[2], s2v, G1b))) * m1;
            float g2v = (G2[0] + fmaf(G2[1], s1v, fmaf(G2[2], s2v, G2b))) * m2;
            S2_1 = fmaf(g1v, DT_C, s1v); S2_2 = fmaf(g2v, DT_C, s2v);
        }
        {
            float g1v = (G1[0] + fmaf(G1[1], S2_1, fmaf(G1[2], S2_2, G1b))) * m1;
            float g2v = (G2[0] + fmaf(G2[1], S2_1, fmaf(G2[2], S2_2, G2b))) * m2;
            S3_1 = fmaf(g1v, DT_C, S2_1); S3_2 = fmaf(g2v, DT_C, S2_2);
        }
        {
            float g1v = (G1[0] + fmaf(G1[1], S3_1, fmaf(G1[2], S3_2, G1b))) * m1;
            float g2v = (G2[0] + fmaf(G2[1], S3_1, fmaf(G2[2], S3_2, G2b))) * m2;
            S4_1 = fmaf(g1v, DT_C, S3_1); S4_2 = fmaf(g2v, DT_C, S3_2);
        }
        float vd1 = (F1[0] + fmaf(F1[1], S4_1, fmaf(F1[2], S4_2, F1b))) * m1;
        float vd2 = (F2[0] + fmaf(F2[1], S4_1, fmaf(F2[2], S4_2, F2b))) * m2;

        float4* o = (float4*)(out + (((size_t)b * LSEQ + q) << 3));
        o[0] = make_float4(S2_1 * sc0, S2_2 * sc1, S3_1 * sc0, S3_2 * sc1);
        o[1] = make_float4(S4_1 * sc0, S4_2 * sc1,
                           fmaf(vd1, DT_C, S4_1) * sc0, fmaf(vd2, DT_C, S4_2) * sc1);
    }
}

extern "C" void kernel_launch(void* const* d_in, const int* in_sizes, int n_in,
                              void* d_out, int out_size)
{
    const float* inp = (const float*)d_in[1];
    const float* ipw = (const float*)d_in[2];
    const float* ipb = (const float*)d_in[3];
    const float* opw = (const float*)d_in[4];
    const float* opb = (const float*)d_in[5];
    const float* f1w = (const float*)d_in[6];
    const float* f1b = (const float*)d_in[7];
    const float* f2w = (const float*)d_in[8];
    const float* f2b = (const float*)d_in[9];
    const float* g1w = (const float*)d_in[10];
    const float* g1b = (const float*)d_in[11];
    const float* g2w = (const float*)d_in[12];
    const float* g2b = (const float*)d_in[13];
    const float* m1p = (const float*)d_in[14];
    const float* m2p = (const float*)d_in[15];
    const float* sig = (const float*)d_in[16];
    float* out = (float*)d_out;

    const int smem = (3 * 1024 + 256) * sizeof(float4);   // 52 KB
    cudaFuncSetAttribute(fused_kernel, cudaFuncAttributeMaxDynamicSharedMemorySize, smem);

    dim3 grid(BATCH, NCHUNK);
    fused_kernel<<<grid, TPB, smem>>>(inp, ipw, ipb, opw, opb,
                                      f1w, f1b, f2w, f2b,
                                      g1w, g1b, g2w, g2b,
                                      m1p, m2p, sig, out);
}

// round 9
// speedup vs baseline: 1.1685x; 1.1685x over previous
#include <cuda_runtime.h>

#define LSEQ    2048
#define BATCH   32
#define NPAIR   1024
#define TPB     128
#define NCHUNK  16
#define NSEG    4
#define SEGMAX  256
#define DT_C    0.01f
#define EPS_C   1e-5f
#define QS_C    (1.4426950408889634f * 0.57735026918962576f)  // log2e/sqrt(3)

typedef unsigned long long ull;

__device__ __forceinline__ ull fma2(ull a, ull b, ull c) {
    ull d; asm("fma.rn.f32x2 %0, %1, %2, %3;" : "=l"(d) : "l"(a), "l"(b), "l"(c)); return d;
}
__device__ __forceinline__ ull mul2(ull a, ull b) {
    ull d; asm("mul.rn.f32x2 %0, %1, %2;" : "=l"(d) : "l"(a), "l"(b)); return d;
}
__device__ __forceinline__ ull add2(ull a, ull b) {
    ull d; asm("add.rn.f32x2 %0, %1, %2;" : "=l"(d) : "l"(a), "l"(b)); return d;
}
__device__ __forceinline__ ull pk2(float lo, float hi) {
    ull r; asm("mov.b64 %0, {%1, %2};" : "=l"(r) : "f"(lo), "f"(hi)); return r;
}
__device__ __forceinline__ void up2(ull v, float& lo, float& hi) {
    asm("mov.b64 {%0, %1}, %2;" : "=f"(lo), "=f"(hi) : "l"(v));
}
__device__ __forceinline__ float ex2f(float x) {
    float y; asm("ex2.approx.ftz.f32 %0, %1;" : "=f"(y) : "f"(x)); return y;
}

// partials: [b][q][seg], 64B contiguous per token for the combine kernel
__device__ float4 g_part[BATCH][LSEQ][NSEG];

// ======== kernel 1: fused projection + attention partials (K-split x4) ========
__global__ void __launch_bounds__(TPB, 8)
attn_part_kernel(const float* __restrict__ inp,
                 const float* __restrict__ ipw, const float* __restrict__ ipb,
                 const float* __restrict__ sig)
{
    __shared__ float4 sP[SEGMAX];   // relative index j = 0..segl-1
    __shared__ float4 sQ[SEGMAX];
    __shared__ float4 sR[SEGMAX];

    const int b = blockIdx.x;
    const int s = blockIdx.y;
    const int c = (NCHUNK - 1) - blockIdx.z;        // long chunks first
    const int t = threadIdx.x;
    const int q = c * TPB + t;

    const int segl = (c + 1) * (NPAIR / NCHUNK / NSEG);   // (c+1)*16
    const int s0 = s * segl;

    const float inv0 = 1.0f / (__ldg(&sig[0]) + EPS_C);
    const float inv1 = 1.0f / (__ldg(&sig[1]) + EPS_C);
    const float* xb = inp + ((size_t)b * LSEQ) * 3;

    // ---- project this segment's K/V pairs into smem (relative index) ----
    {
        float WK[9], WV[9], BK[3], BV[3];
        #pragma unroll
        for (int k = 0; k < 9; k++) { WK[k] = __ldg(&ipw[9 + k]); WV[k] = __ldg(&ipw[18 + k]); }
        #pragma unroll
        for (int k = 0; k < 3; k++) { BK[k] = __ldg(&ipb[3 + k]); BV[k] = __ldg(&ipb[6 + k]); }

        for (int j = t; j < segl; j += TPB) {
            const float2* xp = (const float2*)(xb + 6 * (s0 + j));
            float2 u0 = __ldg(&xp[0]);
            float2 u1 = __ldg(&xp[1]);
            float2 u2 = __ldg(&xp[2]);
            float xe0 = u0.x, xe1 = u0.y * inv0, xe2 = u1.x * inv1;
            float xo0 = u1.y, xo1 = u2.x * inv0, xo2 = u2.y * inv1;
            float ke[3], ko[3], ve[3], vo[3];
            #pragma unroll
            for (int r = 0; r < 3; r++) {
                ke[r] = fmaf(WK[3*r], xe0, fmaf(WK[3*r+1], xe1, fmaf(WK[3*r+2], xe2, BK[r])));
                ko[r] = fmaf(WK[3*r], xo0, fmaf(WK[3*r+1], xo1, fmaf(WK[3*r+2], xo2, BK[r])));
                ve[r] = fmaf(WV[3*r], xe0, fmaf(WV[3*r+1], xe1, fmaf(WV[3*r+2], xe2, BV[r])));
                vo[r] = fmaf(WV[3*r], xo0, fmaf(WV[3*r+1], xo1, fmaf(WV[3*r+2], xo2, BV[r])));
            }
            sP[j] = make_float4(ke[0], ko[0], ke[1], ko[1]);
            sQ[j] = make_float4(ke[2], ko[2], ve[0], vo[0]);
            sR[j] = make_float4(ve[1], vo[1], ve[2], vo[2]);
        }
    }

    // ---- own query ----
    ull qp0, qp1, qp2;
    {
        const float* xq = xb + q * 3;
        float x0 = __ldg(&xq[0]), x1 = __ldg(&xq[1]) * inv0, x2 = __ldg(&xq[2]) * inv1;
        float q0 = fmaf(__ldg(&ipw[0]), x0, fmaf(__ldg(&ipw[1]), x1, fmaf(__ldg(&ipw[2]), x2, __ldg(&ipb[0])))) * QS_C;
        float q1 = fmaf(__ldg(&ipw[3]), x0, fmaf(__ldg(&ipw[4]), x1, fmaf(__ldg(&ipw[5]), x2, __ldg(&ipb[1])))) * QS_C;
        float q2 = fmaf(__ldg(&ipw[6]), x0, fmaf(__ldg(&ipw[7]), x1, fmaf(__ldg(&ipw[8]), x2, __ldg(&ipb[2])))) * QS_C;
        qp0 = pk2(q0, q0); qp1 = pk2(q1, q1); qp2 = pk2(q2, q2);
    }

    __syncthreads();

    // causal bounds (relative j; absolute pair id gp = s0 + j)
    const int qbase = c * TPB + (t & ~31);
    const int lbmin = (qbase - 1) >> 1;
    const int lamax = (qbase + 31) >> 1;
    const int B1 = min(segl, max(0, lbmin + 1 - s0));   // unmasked for all lanes
    const int B2 = min(segl, max(0, lamax + 1 - s0));   // diagonal band end
    const int la = q >> 1;
    const int lb = (q - 1) >> 1;

    const ulonglong2* pP = (const ulonglong2*)sP;
    const ulonglong2* pQ = (const ulonglong2*)sQ;
    const ulonglong2* pR = (const ulonglong2*)sR;

    // dual accumulator sets break the serial dependency chain
    ull sumA = 0ull, a0A = 0ull, a1A = 0ull, a2A = 0ull;
    ull sumB = 0ull, a0B = 0ull, a1B = 0ull, a2B = 0ull;

    int j = 0;
    for (; j + 2 <= B1; j += 2) {
        ulonglong2 P0 = pP[j],   Q0 = pQ[j],   R0 = pR[j];
        ulonglong2 P1 = pP[j+1], Q1 = pQ[j+1], R1 = pR[j+1];
        ull sc0 = fma2(P0.x, qp0, fma2(P0.y, qp1, mul2(Q0.x, qp2)));
        ull sc1 = fma2(P1.x, qp0, fma2(P1.y, qp1, mul2(Q1.x, qp2)));
        float se0, so0, se1, so1;
        up2(sc0, se0, so0);
        up2(sc1, se1, so1);
        ull p0 = pk2(ex2f(se0), ex2f(so0));
        ull p1 = pk2(ex2f(se1), ex2f(so1));
        sumA = add2(sumA, p0);
        a0A = fma2(p0, Q0.y, a0A);
        a1A = fma2(p0, R0.x, a1A);
        a2A = fma2(p0, R0.y, a2A);
        sumB = add2(sumB, p1);
        a0B = fma2(p1, Q1.y, a0B);
        a1B = fma2(p1, R1.x, a1B);
        a2B = fma2(p1, R1.y, a2B);
    }
    if (j < B1) {                                  // odd bulk tail
        ulonglong2 Pv = pP[j], Qv = pQ[j], Rv = pR[j];
        ull sc = fma2(Pv.x, qp0, fma2(Pv.y, qp1, mul2(Qv.x, qp2)));
        float se, so; up2(sc, se, so);
        ull p = pk2(ex2f(se), ex2f(so));
        sumA = add2(sumA, p);
        a0A = fma2(p, Qv.y, a0A);
        a1A = fma2(p, Rv.x, a1A);
        a2A = fma2(p, Rv.y, a2A);
        j++;
    }
    for (; j < B2; j++) {                          // diagonal band (<=17 iters)
        int gp = s0 + j;
        ulonglong2 Pv = pP[j], Qv = pQ[j], Rv = pR[j];
        ull sc = fma2(Pv.x, qp0, fma2(Pv.y, qp1, mul2(Qv.x, qp2)));
        float se, so; up2(sc, se, so);
        float plo = (gp <= la) ? ex2f(se) : 0.0f;
        float phi = (gp <= lb) ? ex2f(so) : 0.0f;
        ull p = pk2(plo, phi);
        sumA = add2(sumA, p);
        a0A = fma2(p, Qv.y, a0A);
        a1A = fma2(p, Rv.x, a1A);
        a2A = fma2(p, Rv.y, a2A);
    }

    ull sum2 = add2(sumA, sumB);
    ull a02 = add2(a0A, a0B);
    ull a12 = add2(a1A, a1B);
    ull a22 = add2(a2A, a2B);

    float sl, sh, c0l, c0h, c1l, c1h, c2l, c2h;
    up2(sum2, sl, sh); up2(a02, c0l, c0h); up2(a12, c1l, c1h); up2(a22, c2l, c2h);
    g_part[b][q][s] = make_float4(sl + sh, c0l + c0h, c1l + c1h, c2l + c2h);
}

// ======== kernel 2: combine + out-proj + ODE epilogue ========
__global__ void __launch_bounds__(TPB)
combine_kernel(const float* __restrict__ opw, const float* __restrict__ opb,
               const float* __restrict__ f1w, const float* __restrict__ f1b,
               const float* __restrict__ f2w, const float* __restrict__ f2b,
               const float* __restrict__ g1w, const float* __restrict__ g1b,
               const float* __restrict__ g2w, const float* __restrict__ g2b,
               const float* __restrict__ m1p, const float* __restrict__ m2p,
               const float* __restrict__ sig,
               float* __restrict__ out)
{
    int idx = blockIdx.x * TPB + threadIdx.x;   // 0 .. BATCH*LSEQ-1
    int b = idx >> 11, q = idx & (LSEQ - 1);

    const float4* gp = g_part[b][q];
    float4 A = gp[0];
    float4 Bp = gp[1];
    float4 C = gp[2];
    float4 D = gp[3];
    float cs = (A.x + Bp.x) + (C.x + D.x);
    float c0 = (A.y + Bp.y) + (C.y + D.y);
    float c1 = (A.z + Bp.z) + (C.z + D.z);
    float c2 = (A.w + Bp.w) + (C.w + D.w);

    const float sc0 = __ldg(&sig[0]) + EPS_C;
    const float sc1 = __ldg(&sig[1]) + EPS_C;
    float wo[9];
    #pragma unroll
    for (int i = 0; i < 9; i++) wo[i] = __ldg(&opw[i]);
    const float bo1 = __ldg(&opb[1]), bo2 = __ldg(&opb[2]);
    const float m1 = __ldg(m1p), m2 = __ldg(m2p);
    float F1[3], F2[3], G1[3], G2[3];
    #pragma unroll
    for (int i = 0; i < 3; i++) {
        F1[i] = __ldg(&f1w[i]); F2[i] = __ldg(&f2w[i]);
        G1[i] = __ldg(&g1w[i]); G2[i] = __ldg(&g2w[i]);
    }
    const float F1b = __ldg(f1b), F2b = __ldg(f2b), G1b = __ldg(g1b), G2b = __ldg(g2b);

    float inv = 1.0f / cs;
    float x0 = c0 * inv, x1 = c1 * inv, x2 = c2 * inv;
    float s1 = fmaf(wo[3], x0, fmaf(wo[4], x1, fmaf(wo[5], x2, bo1)));
    float s2 = fmaf(wo[6], x0, fmaf(wo[7], x1, fmaf(wo[8], x2, bo2)));

    float S2_1, S2_2, S3_1, S3_2, S4_1, S4_2;
    {
        float g1v = (G1[0] + fmaf(G1[1], s1, fmaf(G1[2], s2, G1b))) * m1;
        float g2v = (G2[0] + fmaf(G2[1], s1, fmaf(G2[2], s2, G2b))) * m2;
        S2_1 = fmaf(g1v, DT_C, s1); S2_2 = fmaf(g2v, DT_C, s2);
    }
    {
        float g1v = (G1[0] + fmaf(G1[1], S2_1, fmaf(G1[2], S2_2, G1b))) * m1;
        float g2v = (G2[0] + fmaf(G2[1], S2_1, fmaf(G2[2], S2_2, G2b))) * m2;
        S3_1 = fmaf(g1v, DT_C, S2_1); S3_2 = fmaf(g2v, DT_C, S2_2);
    }
    {
        float g1v = (G1[0] + fmaf(G1[1], S3_1, fmaf(G1[2], S3_2, G1b))) * m1;
        float g2v = (G2[0] + fmaf(G2[1], S3_1, fmaf(G2[2], S3_2, G2b))) * m2;
        S4_1 = fmaf(g1v, DT_C, S3_1); S4_2 = fmaf(g2v, DT_C, S3_2);
    }
    float vd1 = (F1[0] + fmaf(F1[1], S4_1, fmaf(F1[2], S4_2, F1b))) * m1;
    float vd2 = (F2[0] + fmaf(F2[1], S4_1, fmaf(F2[2], S4_2, F2b))) * m2;

    float4* o = (float4*)(out + ((size_t)idx << 3));
    o[0] = make_float4(S2_1 * sc0, S2_2 * sc1, S3_1 * sc0, S3_2 * sc1);
    o[1] = make_float4(S4_1 * sc0, S4_2 * sc1,
                       fmaf(vd1, DT_C, S4_1) * sc0, fmaf(vd2, DT_C, S4_2) * sc1);
}

extern "C" void kernel_launch(void* const* d_in, const int* in_sizes, int n_in,
                              void* d_out, int out_size)
{
    const float* inp = (const float*)d_in[1];
    const float* ipw = (const float*)d_in[2];
    const float* ipb = (const float*)d_in[3];
    const float* opw = (const float*)d_in[4];
    const float* opb = (const float*)d_in[5];
    const float* f1w = (const float*)d_in[6];
    const float* f1b = (const float*)d_in[7];
    const float* f2w = (const float*)d_in[8];
    const float* f2b = (const float*)d_in[9];
    const float* g1w = (const float*)d_in[10];
    const float* g1b = (const float*)d_in[11];
    const float* g2w = (const float*)d_in[12];
    const float* g2b = (const float*)d_in[13];
    const float* m1p = (const float*)d_in[14];
    const float* m2p = (const float*)d_in[15];
    const float* sig = (const float*)d_in[16];
    float* out = (float*)d_out;

    dim3 grid(BATCH, NSEG, NCHUNK);
    attn_part_kernel<<<grid, TPB>>>(inp, ipw, ipb, sig);

    combine_kernel<<<(BATCH * LSEQ) / TPB, TPB>>>(opw, opb, f1w, f1b, f2w, f2b,
                                                  g1w, g1b, g2w, g2b,
                                                  m1p, m2p, sig, out);
}

// round 10
// speedup vs baseline: 1.2216x; 1.0454x over previous
#include <cuda_runtime.h>

#define LSEQ    2048
#define BATCH   32
#define NPAIR   1024
#define TPB     128
#define NCHUNK  16
#define NSEG    4
#define SEGMAX  256
#define DT_C    0.01f
#define EPS_C   1e-5f
#define QS_C    (1.4426950408889634f * 0.57735026918962576f)  // log2e/sqrt(3)

typedef unsigned long long ull;

__device__ __forceinline__ ull fma2(ull a, ull b, ull c) {
    ull d; asm("fma.rn.f32x2 %0, %1, %2, %3;" : "=l"(d) : "l"(a), "l"(b), "l"(c)); return d;
}
__device__ __forceinline__ ull mul2(ull a, ull b) {
    ull d; asm("mul.rn.f32x2 %0, %1, %2;" : "=l"(d) : "l"(a), "l"(b)); return d;
}
__device__ __forceinline__ ull add2(ull a, ull b) {
    ull d; asm("add.rn.f32x2 %0, %1, %2;" : "=l"(d) : "l"(a), "l"(b)); return d;
}
__device__ __forceinline__ ull pk2(float lo, float hi) {
    ull r; asm("mov.b64 %0, {%1, %2};" : "=l"(r) : "f"(lo), "f"(hi)); return r;
}
__device__ __forceinline__ void up2(ull v, float& lo, float& hi) {
    asm("mov.b64 {%0, %1}, %2;" : "=f"(lo), "=f"(hi) : "l"(v));
}
__device__ __forceinline__ float ex2f(float x) {
    float y; asm("ex2.approx.ftz.f32 %0, %1;" : "=f"(y) : "f"(x)); return y;
}

// partials [b][q][seg] (64B/token) + arrival counters (zero-init; reset after use)
__device__ float4   g_part[BATCH][LSEQ][NSEG];
__device__ unsigned g_cnt[BATCH][LSEQ];

// ======== single launch: projection + attention partials + last-arriver epilogue ========
__global__ void __launch_bounds__(TPB, 8)
attn_kernel(const float* __restrict__ inp,
            const float* __restrict__ ipw, const float* __restrict__ ipb,
            const float* __restrict__ opw, const float* __restrict__ opb,
            const float* __restrict__ f1w, const float* __restrict__ f1b,
            const float* __restrict__ f2w, const float* __restrict__ f2b,
            const float* __restrict__ g1w, const float* __restrict__ g1b,
            const float* __restrict__ g2w, const float* __restrict__ g2b,
            const float* __restrict__ m1p, const float* __restrict__ m2p,
            const float* __restrict__ sig,
            float* __restrict__ out)
{
    __shared__ float4 sP[SEGMAX];   // relative index j = 0..segl-1
    __shared__ float4 sQ[SEGMAX];
    __shared__ float4 sR[SEGMAX];

    const int b = blockIdx.x;
    const int s = blockIdx.y;
    const int c = (NCHUNK - 1) - blockIdx.z;        // long chunks first
    const int t = threadIdx.x;
    const int q = c * TPB + t;

    const int segl = (c + 1) * (NPAIR / NCHUNK / NSEG);   // (c+1)*16
    const int s0 = s * segl;

    const float inv0 = 1.0f / (__ldg(&sig[0]) + EPS_C);
    const float inv1 = 1.0f / (__ldg(&sig[1]) + EPS_C);
    const float* xb = inp + ((size_t)b * LSEQ) * 3;

    // ---- project this segment's K/V pairs into smem ----
    {
        float WK[9], WV[9], BK[3], BV[3];
        #pragma unroll
        for (int k = 0; k < 9; k++) { WK[k] = __ldg(&ipw[9 + k]); WV[k] = __ldg(&ipw[18 + k]); }
        #pragma unroll
        for (int k = 0; k < 3; k++) { BK[k] = __ldg(&ipb[3 + k]); BV[k] = __ldg(&ipb[6 + k]); }

        for (int j = t; j < segl; j += TPB) {
            const float2* xp = (const float2*)(xb + 6 * (s0 + j));
            float2 u0 = __ldg(&xp[0]);
            float2 u1 = __ldg(&xp[1]);
            float2 u2 = __ldg(&xp[2]);
            float xe0 = u0.x, xe1 = u0.y * inv0, xe2 = u1.x * inv1;
            float xo0 = u1.y, xo1 = u2.x * inv0, xo2 = u2.y * inv1;
            float ke[3], ko[3], ve[3], vo[3];
            #pragma unroll
            for (int r = 0; r < 3; r++) {
                ke[r] = fmaf(WK[3*r], xe0, fmaf(WK[3*r+1], xe1, fmaf(WK[3*r+2], xe2, BK[r])));
                ko[r] = fmaf(WK[3*r], xo0, fmaf(WK[3*r+1], xo1, fmaf(WK[3*r+2], xo2, BK[r])));
                ve[r] = fmaf(WV[3*r], xe0, fmaf(WV[3*r+1], xe1, fmaf(WV[3*r+2], xe2, BV[r])));
                vo[r] = fmaf(WV[3*r], xo0, fmaf(WV[3*r+1], xo1, fmaf(WV[3*r+2], xo2, BV[r])));
            }
            sP[j] = make_float4(ke[0], ko[0], ke[1], ko[1]);
            sQ[j] = make_float4(ke[2], ko[2], ve[0], vo[0]);
            sR[j] = make_float4(ve[1], vo[1], ve[2], vo[2]);
        }
    }

    // ---- own query ----
    ull qp0, qp1, qp2;
    {
        const float* xq = xb + q * 3;
        float x0 = __ldg(&xq[0]), x1 = __ldg(&xq[1]) * inv0, x2 = __ldg(&xq[2]) * inv1;
        float q0 = fmaf(__ldg(&ipw[0]), x0, fmaf(__ldg(&ipw[1]), x1, fmaf(__ldg(&ipw[2]), x2, __ldg(&ipb[0])))) * QS_C;
        float q1 = fmaf(__ldg(&ipw[3]), x0, fmaf(__ldg(&ipw[4]), x1, fmaf(__ldg(&ipw[5]), x2, __ldg(&ipb[1])))) * QS_C;
        float q2 = fmaf(__ldg(&ipw[6]), x0, fmaf(__ldg(&ipw[7]), x1, fmaf(__ldg(&ipw[8]), x2, __ldg(&ipb[2])))) * QS_C;
        qp0 = pk2(q0, q0); qp1 = pk2(q1, q1); qp2 = pk2(q2, q2);
    }

    __syncthreads();

    // causal bounds (relative j; absolute pair id gp = s0 + j)
    const int qbase = c * TPB + (t & ~31);
    const int lbmin = (qbase - 1) >> 1;
    const int lamax = (qbase + 31) >> 1;
    const int B1 = min(segl, max(0, lbmin + 1 - s0));   // unmasked for all lanes
    const int B2 = min(segl, max(0, lamax + 1 - s0));   // diagonal band end
    const int la = q >> 1;
    const int lb = (q - 1) >> 1;

    const ulonglong2* pP = (const ulonglong2*)sP;
    const ulonglong2* pQ = (const ulonglong2*)sQ;
    const ulonglong2* pR = (const ulonglong2*)sR;

    ull sum2 = 0ull, a02 = 0ull, a12 = 0ull, a22 = 0ull;

    #pragma unroll 4
    for (int j = 0; j < B1; j++) {                  // unmasked bulk
        ulonglong2 Pv = pP[j];
        ulonglong2 Qv = pQ[j];
        ulonglong2 Rv = pR[j];
        ull sc = fma2(Pv.x, qp0, fma2(Pv.y, qp1, mul2(Qv.x, qp2)));
        float se, so; up2(sc, se, so);
        ull p = pk2(ex2f(se), ex2f(so));
        sum2 = add2(sum2, p);
        a02 = fma2(p, Qv.y, a02);
        a12 = fma2(p, Rv.x, a12);
        a22 = fma2(p, Rv.y, a22);
    }
    for (int j = B1; j < B2; j++) {                 // diagonal band (<=17 iters)
        int gp = s0 + j;
        ulonglong2 Pv = pP[j];
        ulonglong2 Qv = pQ[j];
        ulonglong2 Rv = pR[j];
        ull sc = fma2(Pv.x, qp0, fma2(Pv.y, qp1, mul2(Qv.x, qp2)));
        float se, so; up2(sc, se, so);
        float plo = (gp <= la) ? ex2f(se) : 0.0f;
        float phi = (gp <= lb) ? ex2f(so) : 0.0f;
        ull p = pk2(plo, phi);
        sum2 = add2(sum2, p);
        a02 = fma2(p, Qv.y, a02);
        a12 = fma2(p, Rv.x, a12);
        a22 = fma2(p, Rv.y, a22);
    }

    float sl, sh, c0l, c0h, c1l, c1h, c2l, c2h;
    up2(sum2, sl, sh); up2(a02, c0l, c0h); up2(a12, c1l, c1h); up2(a22, c2l, c2h);
    g_part[b][q][s] = make_float4(sl + sh, c0l + c0h, c1l + c1h, c2l + c2h);

    // ---- last-arriver combine + epilogue ----
    __threadfence();                                 // release partial
    unsigned old = atomicAdd(&g_cnt[b][q], 1u);
    if (old == NSEG - 1) {
        g_cnt[b][q] = 0;                             // reset for next graph replay
        __threadfence();                             // acquire others' partials

        const float4* gp = g_part[b][q];
        float4 A = gp[0], Bp = gp[1], C = gp[2], D = gp[3];
        float cs = (A.x + Bp.x) + (C.x + D.x);
        float c0 = (A.y + Bp.y) + (C.y + D.y);
        float c1 = (A.z + Bp.z) + (C.z + D.z);
        float c2 = (A.w + Bp.w) + (C.w + D.w);

        const float sc0 = __ldg(&sig[0]) + EPS_C;
        const float sc1 = __ldg(&sig[1]) + EPS_C;
        float wo[9];
        #pragma unroll
        for (int i = 0; i < 9; i++) wo[i] = __ldg(&opw[i]);
        const float bo1 = __ldg(&opb[1]), bo2 = __ldg(&opb[2]);
        const float m1 = __ldg(m1p), m2 = __ldg(m2p);
        float F1[3], F2[3], G1[3], G2[3];
        #pragma unroll
        for (int i = 0; i < 3; i++) {
            F1[i] = __ldg(&f1w[i]); F2[i] = __ldg(&f2w[i]);
            G1[i] = __ldg(&g1w[i]); G2[i] = __ldg(&g2w[i]);
        }
        const float F1b = __ldg(f1b), F2b = __ldg(f2b), G1b = __ldg(g1b), G2b = __ldg(g2b);

        float inv = 1.0f / cs;
        float x0 = c0 * inv, x1 = c1 * inv, x2 = c2 * inv;
        float s1v = fmaf(wo[3], x0, fmaf(wo[4], x1, fmaf(wo[5], x2, bo1)));
        float s2v = fmaf(wo[6], x0, fmaf(wo[7], x1, fmaf(wo[8], x2, bo2)));

        float S2_1, S2_2, S3_1, S3_2, S4_1, S4_2;
        {
            float g1v = (G1[0] + fmaf(G1[1], s1v, fmaf(G1[2], s2v, G1b))) * m1;
            float g2v = (G2[0] + fmaf(G2[1], s1v, fmaf(G2[2], s2v, G2b))) * m2;
            S2_1 = fmaf(g1v, DT_C, s1v); S2_2 = fmaf(g2v, DT_C, s2v);
        }
        {
            float g1v = (G1[0] + fmaf(G1[1], S2_1, fmaf(G1[2], S2_2, G1b))) * m1;
            float g2v = (G2[0] + fmaf(G2[1], S2_1, fmaf(G2[2], S2_2, G2b))) * m2;
            S3_1 = fmaf(g1v, DT_C, S2_1); S3_2 = fmaf(g2v, DT_C, S2_2);
        }
        {
            float g1v = (G1[0] + fmaf(G1[1], S3_1, fmaf(G1[2], S3_2, G1b))) * m1;
            float g2v = (G2[0] + fmaf(G2[1], S3_1, fmaf(G2[2], S3_2, G2b))) * m2;
            S4_1 = fmaf(g1v, DT_C, S3_1); S4_2 = fmaf(g2v, DT_C, S3_2);
        }
        float vd1 = (F1[0] + fmaf(F1[1], S4_1, fmaf(F1[2], S4_2, F1b))) * m1;
        float vd2 = (F2[0] + fmaf(F2[1], S4_1, fmaf(F2[2], S4_2, F2b))) * m2;

        float4* o = (float4*)(out + (((size_t)b * LSEQ + q) << 3));
        o[0] = make_float4(S2_1 * sc0, S2_2 * sc1, S3_1 * sc0, S3_2 * sc1);
        o[1] = make_float4(S4_1 * sc0, S4_2 * sc1,
                           fmaf(vd1, DT_C, S4_1) * sc0, fmaf(vd2, DT_C, S4_2) * sc1);
    }
}

extern "C" void kernel_launch(void* const* d_in, const int* in_sizes, int n_in,
                              void* d_out, int out_size)
{
    const float* inp = (const float*)d_in[1];
    const float* ipw = (const float*)d_in[2];
    const float* ipb = (const float*)d_in[3];
    const float* opw = (const float*)d_in[4];
    const float* opb = (const float*)d_in[5];
    const float* f1w = (const float*)d_in[6];
    const float* f1b = (const float*)d_in[7];
    const float* f2w = (const float*)d_in[8];
    const float* f2b = (const float*)d_in[9];
    const float* g1w = (const float*)d_in[10];
    const float* g1b = (const float*)d_in[11];
    const float* g2w = (const float*)d_in[12];
    const float* g2b = (const float*)d_in[13];
    const float* m1p = (const float*)d_in[14];
    const float* m2p = (const float*)d_in[15];
    const float* sig = (const float*)d_in[16];
    float* out = (float*)d_out;

    dim3 grid(BATCH, NSEG, NCHUNK);
    attn_kernel<<<grid, TPB>>>(inp, ipw, ipb, opw, opb,
                               f1w, f1b, f2w, f2b,
                               g1w, g1b, g2w, g2b,
                               m1p, m2p, sig, out);
}